// round 8
// baseline (speedup 1.0000x reference)
#include <cuda_runtime.h>
#include <cstdint>

// Problem constants (fixed shapes from reference setup_inputs)
#define T_STEPS 4
#define B_BATCH 32            // TB / T = 128/4
#define N_SEQ   1024
#define CIN     512
#define COUT    512
#define M_TOTAL (T_STEPS * B_BATCH * N_SEQ)   // 131072 rows

// Scratch in device globals (no allocations allowed)
__device__ float g_y[(size_t)M_TOTAL * COUT];      // 268 MB GEMM output
__device__ float g_wt[CIN][COUT];                   // W transposed: [k][o], 1 MB
#define NPART 1024
__device__ float g_psum[NPART * COUT];
__device__ float g_psq [NPART * COUT];
__device__ float g_mean[COUT];
__device__ float g_rstd[COUT];

// ---------------------------------------------------------------------------
// Packed f32x2 helpers (per-lane bitwise-identical to scalar fmaf).
// ---------------------------------------------------------------------------
__device__ __forceinline__ unsigned long long pack_dup(float a) {
    unsigned long long u;
    asm("mov.b64 %0, {%1, %1};" : "=l"(u) : "f"(a));
    return u;
}
__device__ __forceinline__ void fma2(unsigned long long& acc,
                                     unsigned long long a,
                                     unsigned long long b) {
    asm("fma.rn.f32x2 %0, %1, %2, %0;" : "+l"(acc) : "l"(a), "l"(b));
}
__device__ __forceinline__ float2 unpack2(unsigned long long u) {
    float lo, hi;
    asm("mov.b64 {%0, %1}, %2;" : "=f"(lo), "=f"(hi) : "l"(u));
    return make_float2(lo, hi);
}
__device__ __forceinline__ uint32_t smem_u32(const void* p) {
    uint32_t a;
    asm("{ .reg .u64 t; cvta.to.shared.u64 t, %1; cvt.u32.u64 %0, t; }" : "=r"(a) : "l"(p));
    return a;
}
__device__ __forceinline__ void cp_async16(uint32_t dst, const void* src) {
    asm volatile("cp.async.cg.shared.global [%0], [%1], 16;" :: "r"(dst), "l"(src) : "memory");
}

// ---------------------------------------------------------------------------
// Tiled transpose: g_wt[k][o] = W[o][k].
// ---------------------------------------------------------------------------
__global__ void __launch_bounds__(256)
wt_k(const float* __restrict__ W) {
    __shared__ float t[32][33];
    const int bo = blockIdx.x * 32;
    const int bk = blockIdx.y * 32;
    const int lx = threadIdx.x & 31;
    const int ly = threadIdx.x >> 5;
#pragma unroll
    for (int i = 0; i < 4; i++)
        t[ly + 8 * i][lx] = W[(size_t)(bo + ly + 8 * i) * CIN + bk + lx];
    __syncthreads();
#pragma unroll
    for (int i = 0; i < 4; i++)
        g_wt[bk + ly + 8 * i][bo + lx] = t[lx][ly + 8 * i];
}

// ---------------------------------------------------------------------------
// SGEMM: C[m,o] = sum_k A[m,k]*W[o,k], k strictly sequential fp32 per output
// (must reproduce reference rounding; tensor-core adder trees flip spikes).
// 128x128x32 tile (BK=32 halves barrier count vs BK=16), 256 threads,
// 8x8/thread, double-buffered DYNAMIC smem (67.6KB), 2 CTAs/SM.
// W tiles via cp.async from g_wt; A prefetched in two 8-reg halves, each
// hidden under a 16-kk compute block (keeps reg peak ~same as BK=16 build).
// ---------------------------------------------------------------------------
#define BM 128
#define BNb 128
#define BK 32
#define SPAD 4
#define AROW (BM + SPAD)            // 132
#define WROW (BNb + SPAD)           // 132
#define ATILE_F (BK * AROW)         // 4224 floats per A buffer
#define WTILE_F (BK * WROW)         // 4224 floats per W buffer
#define DYN_SMEM ((2 * ATILE_F + 2 * WTILE_F) * 4)   // 67584 bytes

__global__ void __launch_bounds__(256, 2)
gemm_k(const float* __restrict__ A) {
    extern __shared__ float dyn[];
    float* Asb = dyn;                       // [2][BK][AROW]
    float* Wsb = dyn + 2 * ATILE_F;         // [2][BK][WROW]

    const int tid = threadIdx.x;
    const int tx = tid & 15;
    const int ty = tid >> 4;
    const int m0 = blockIdx.y * BM;
    const int n0 = blockIdx.x * BNb;

    const int ar0 = ty * 4;
    const int bc0 = tx * 4;

    // A global-load mapping: 4 float4 per thread per stage (2 halves of 2)
    // idx = tid + t*256 : row = idx>>3 (0..127), kv = (idx&7)*4
    const int arow = tid >> 3;           // 0..31 (t adds 32 each)
    const int akv  = (tid & 7) * 4;      // 0,4,..,28
    const float* Aptr = A + (size_t)(m0 + arow) * CIN + akv;
    const size_t row32 = (size_t)32 * CIN;

    // W cp.async mapping: 4 chunks of 16B per thread per stage
    // idx = tid + t*256 : k = idx>>5 (0..31), c4 = idx&31
    const int wk  = tid >> 5;            // 0..7 (t adds 8 each)
    const int wc4 = (tid & 31) * 4;
    const uint32_t ws_u = smem_u32(Wsb);
    const float* wsrc = &g_wt[wk][n0 + wc4];

    auto load_W = [&](int buf, int k0) {
        const uint32_t base = ws_u + (uint32_t)buf * (WTILE_F * 4);
#pragma unroll
        for (int t = 0; t < 4; t++)
            cp_async16(base + ((wk + 8 * t) * WROW + wc4) * 4,
                       wsrc + (size_t)(k0 + 8 * t) * COUT);
        asm volatile("cp.async.commit_group;" ::: "memory");
    };
    auto store_A2 = [&](float* ab, float4 v0, float4 v1, int t0) {
        float* p0 = ab + akv * AROW + (arow + 32 * t0);
        p0[0 * AROW] = v0.x; p0[1 * AROW] = v0.y; p0[2 * AROW] = v0.z; p0[3 * AROW] = v0.w;
        float* p1 = ab + akv * AROW + (arow + 32 * (t0 + 1));
        p1[0 * AROW] = v1.x; p1[1 * AROW] = v1.y; p1[2 * AROW] = v1.z; p1[3 * AROW] = v1.w;
    };

    unsigned long long acc[8][4];
#pragma unroll
    for (int i = 0; i < 8; i++)
#pragma unroll
        for (int j = 0; j < 4; j++) acc[i][j] = 0ULL;

    // ---- prologue: stage 0
    {
        load_W(0, 0);
        float4 v0 = *reinterpret_cast<const float4*>(Aptr);
        float4 v1 = *reinterpret_cast<const float4*>(Aptr + row32);
        store_A2(Asb, v0, v1, 0);
        float4 v2 = *reinterpret_cast<const float4*>(Aptr + 2 * row32);
        float4 v3 = *reinterpret_cast<const float4*>(Aptr + 3 * row32);
        store_A2(Asb, v2, v3, 2);
    }
    asm volatile("cp.async.wait_group 0;" ::: "memory");
    __syncthreads();

    const int NSTAGE = CIN / BK;   // 16

    // one 16-kk compute block
    auto compute16 = [&](const float* As_c, const float* Ws_c, int kbase) {
#pragma unroll
        for (int kk = kbase; kk < kbase + 16; kk++) {
            float4 a0 = *reinterpret_cast<const float4*>(&As_c[kk * AROW + ar0]);
            float4 a1 = *reinterpret_cast<const float4*>(&As_c[kk * AROW + ar0 + 64]);
            float4 b0 = *reinterpret_cast<const float4*>(&Ws_c[kk * WROW + bc0]);
            float4 b1 = *reinterpret_cast<const float4*>(&Ws_c[kk * WROW + bc0 + 64]);
            unsigned long long bp[4];
            bp[0] = *reinterpret_cast<unsigned long long*>(&b0.x);
            bp[1] = *reinterpret_cast<unsigned long long*>(&b0.z);
            bp[2] = *reinterpret_cast<unsigned long long*>(&b1.x);
            bp[3] = *reinterpret_cast<unsigned long long*>(&b1.z);
            const float a[8] = {a0.x, a0.y, a0.z, a0.w, a1.x, a1.y, a1.z, a1.w};
#pragma unroll
            for (int i = 0; i < 8; i++) {
                const unsigned long long ap = pack_dup(a[i]);
#pragma unroll
                for (int jp = 0; jp < 4; jp++)
                    fma2(acc[i][jp], ap, bp[jp]);
            }
        }
    };

#pragma unroll 1
    for (int s = 0; s < NSTAGE; s++) {
        const int cur = s & 1;
        const int nxt = cur ^ 1;
        const float* As_c = Asb + cur * ATILE_F;
        const float* Ws_c = Wsb + cur * WTILE_F;
        float* As_n = Asb + nxt * ATILE_F;
        const bool more = (s + 1 < NSTAGE);
        const int koff = (s + 1) * BK;

        if (more) load_W(nxt, koff);

        // half 1: prefetch A rows 0..63 of next stage, hidden under 16 kk
        float4 v0, v1;
        if (more) {
            v0 = *reinterpret_cast<const float4*>(Aptr + koff);
            v1 = *reinterpret_cast<const float4*>(Aptr + row32 + koff);
        }
        compute16(As_c, Ws_c, 0);
        if (more) store_A2(As_n, v0, v1, 0);

        // half 2: prefetch A rows 64..127, hidden under remaining 16 kk
        if (more) {
            v0 = *reinterpret_cast<const float4*>(Aptr + 2 * row32 + koff);
            v1 = *reinterpret_cast<const float4*>(Aptr + 3 * row32 + koff);
        }
        compute16(As_c, Ws_c, 16);
        if (more) {
            store_A2(As_n, v0, v1, 2);
            asm volatile("cp.async.wait_group 0;" ::: "memory");
            __syncthreads();
        }
    }

    // unpack accumulators
    float acc_f[8][8];
#pragma unroll
    for (int i = 0; i < 8; i++)
#pragma unroll
        for (int jp = 0; jp < 4; jp++) {
            float2 v = unpack2(acc[i][jp]);
            acc_f[i][2 * jp + 0] = v.x;
            acc_f[i][2 * jp + 1] = v.y;
        }

    // ---- store C tile
#pragma unroll
    for (int ih = 0; ih < 2; ih++) {
#pragma unroll
        for (int i = 0; i < 4; i++) {
            const size_t m = (size_t)(m0 + ih * 64 + ar0 + i);
            const int ia = ih * 4 + i;
            float4 v0 = make_float4(acc_f[ia][0], acc_f[ia][1], acc_f[ia][2], acc_f[ia][3]);
            float4 v1 = make_float4(acc_f[ia][4], acc_f[ia][5], acc_f[ia][6], acc_f[ia][7]);
            *reinterpret_cast<float4*>(&g_y[m * COUT + n0 + bc0])      = v0;
            *reinterpret_cast<float4*>(&g_y[m * COUT + n0 + 64 + bc0]) = v1;
        }
    }

    // ---- fused BN partial stats (deterministic tree; reuse smem)
    __syncthreads();
    float* sred = dyn;           // [16][128]
    float* qred = dyn + 2048;    // [16][128]

    float s8[8], q8[8];
#pragma unroll
    for (int j = 0; j < 8; j++) { s8[j] = 0.0f; q8[j] = 0.0f; }
#pragma unroll
    for (int i = 0; i < 8; i++)
#pragma unroll
        for (int j = 0; j < 8; j++) {
            float v = acc_f[i][j];
            s8[j] += v;
            q8[j] = fmaf(v, v, q8[j]);
        }
#pragma unroll
    for (int jh = 0; jh < 2; jh++)
#pragma unroll
        for (int j = 0; j < 4; j++) {
            int c = jh * 64 + bc0 + j;
            sred[ty * 128 + c] = s8[jh * 4 + j];
            qred[ty * 128 + c] = q8[jh * 4 + j];
        }
    __syncthreads();

    if (tid < 128) {
        float s = 0.0f, q = 0.0f;
#pragma unroll
        for (int k = 0; k < 16; k++) {
            s += sred[k * 128 + tid];
            q += qred[k * 128 + tid];
        }
        g_psum[(size_t)blockIdx.y * COUT + n0 + tid] = s;
        g_psq [(size_t)blockIdx.y * COUT + n0 + tid] = q;
    }
}

// Finalize mean / rstd per channel
__global__ void __launch_bounds__(COUT)
stats2_k() {
    const int o = threadIdx.x;
    float s = 0.0f, sq = 0.0f;
    for (int i = 0; i < NPART; i++) {
        s  += g_psum[i * COUT + o];
        sq += g_psq [i * COUT + o];
    }
    const float inv_m = 1.0f / (float)M_TOTAL;
    float mean = s * inv_m;
    float var  = sq * inv_m - mean * mean;
    g_mean[o] = mean;
    g_rstd[o] = rsqrtf(var + 1e-5f);
}

// ---------------------------------------------------------------------------
// Fused BN + multistep LIF + output store (HBM-bound).
// ---------------------------------------------------------------------------
__global__ void __launch_bounds__(256)
lif_k(const float* __restrict__ gamma, const float* __restrict__ beta,
      float* __restrict__ out) {
    const int idx = blockIdx.x * blockDim.x + threadIdx.x;
    const int total = B_BATCH * N_SEQ * COUT;
    if (idx >= total) return;
    const int o = idx & (COUT - 1);

    const float mean = g_mean[o];
    const float rstd = g_rstd[o];
    const float ga = gamma[o];
    const float be = beta[o];

    const size_t stride = (size_t)B_BATCH * N_SEQ * COUT;
    const size_t base = (size_t)idx;

    float v = 0.0f;
#pragma unroll
    for (int t = 0; t < T_STEPS; t++) {
        const size_t off = base + (size_t)t * stride;
        float raw = g_y[off];
        float xt = (raw - mean) * rstd;
        xt = xt * ga + be;
        float d = xt - v;
        v = v + d * 0.5f;
        float sp = (v >= 1.0f) ? 1.0f : 0.0f;
        out[off] = sp;
        v = v * (1.0f - sp);
    }
}

// ---------------------------------------------------------------------------
extern "C" void kernel_launch(void* const* d_in, const int* in_sizes, int n_in,
                              void* d_out, int out_size) {
    const float* x     = (const float*)d_in[0];
    const float* W     = (const float*)d_in[1];
    const float* gamma = (const float*)d_in[2];
    const float* beta  = (const float*)d_in[3];
    float* out = (float*)d_out;

    cudaFuncSetAttribute(gemm_k, cudaFuncAttributeMaxDynamicSharedMemorySize, DYN_SMEM);

    dim3 wt_grid(COUT / 32, CIN / 32);
    wt_k<<<wt_grid, 256>>>(W);

    dim3 gemm_grid(COUT / BNb, M_TOTAL / BM);    // (4, 1024)
    gemm_k<<<gemm_grid, 256, DYN_SMEM>>>(x);

    stats2_k<<<1, COUT>>>();

    const int total = B_BATCH * N_SEQ * COUT;
    lif_k<<<(total + 255) / 256, 256>>>(gamma, beta, out);
}